// round 12
// baseline (speedup 1.0000x reference)
#include <cuda_runtime.h>
#include <cuda_bf16.h>
#include <math.h>
#include <cstdint>

// Problem constants
#define B_    512
#define NS    128
#define IN_   2048
#define MEM_  64
#define OUT_  2048
#define RCOLS 65
#define KO    2176          // IN_ + 2*MEM_
#define NPAD  132

// ------------------------------------------------------------------
// Scratch (device globals)
// ------------------------------------------------------------------
__device__ float g_q  [B_ * MEM_];
__device__ float g_xf [B_];
__device__ float g_xr [B_ * RCOLS];
__device__ float g_W  [IN_ * NPAD];
__device__ __nv_bfloat16 g_Ahi[B_ * KO];       // [512][2176]  (x | act | pas)
__device__ __nv_bfloat16 g_Alo[B_ * KO];
__device__ __nv_bfloat16 g_Bhi[OUT_ * KO];     // [2048][2176] = W_o^T
__device__ __nv_bfloat16 g_Blo[OUT_ * KO];
__device__ __nv_bfloat16 g_WBhi[80 * 64];
__device__ __nv_bfloat16 g_WBlo[80 * 64];

// ------------------------------------------------------------------
// Helpers
// ------------------------------------------------------------------
__device__ __forceinline__ uint32_t smem_u32(const void* p) {
    uint32_t a;
    asm("{ .reg .u64 t; cvta.to.shared.u64 t, %1; cvt.u32.u64 %0, t; }"
        : "=r"(a) : "l"(p));
    return a;
}
__device__ __forceinline__ void cp16(uint32_t dst, const void* src) {
    asm volatile("cp.async.cg.shared.global [%0], [%1], 16;" :: "r"(dst), "l"(src));
}
#define CP_COMMIT()  asm volatile("cp.async.commit_group;" ::: "memory")
#define CP_WAIT(n)   asm volatile("cp.async.wait_group %0;" :: "n"(n) : "memory")

__device__ __forceinline__ void ldm_x4(uint32_t* r, uint32_t addr) {
    asm volatile("ldmatrix.sync.aligned.m8n8.x4.shared.b16 {%0,%1,%2,%3}, [%4];"
        : "=r"(r[0]), "=r"(r[1]), "=r"(r[2]), "=r"(r[3]) : "r"(addr));
}
__device__ __forceinline__ void mma16816(float* c, const uint32_t* a, const uint32_t* b) {
    asm volatile(
        "mma.sync.aligned.m16n8k16.row.col.f32.bf16.bf16.f32 "
        "{%0,%1,%2,%3}, {%4,%5,%6,%7}, {%8,%9}, {%0,%1,%2,%3};"
        : "+f"(c[0]), "+f"(c[1]), "+f"(c[2]), "+f"(c[3])
        : "r"(a[0]), "r"(a[1]), "r"(a[2]), "r"(a[3]), "r"(b[0]), "r"(b[1]));
}
__device__ __forceinline__ void split_bf16(float v, __nv_bfloat16& h, __nv_bfloat16& l) {
    h = __float2bfloat16(v);
    l = __float2bfloat16(v - __bfloat162float(h));
}

// ==================================================================
// Prep kernels
// ==================================================================
#define PACK_TOT (IN_ * NPAD + 80 * 64)
__global__ __launch_bounds__(256) void pack_kernel(
    const float* __restrict__ W_ar, const float* __restrict__ W_f,
    const float* __restrict__ W_r)
{
    int idx = blockIdx.x * 256 + threadIdx.x;
    if (idx >= PACK_TOT) return;
    if (idx < IN_ * NPAD) {
        int k = idx / NPAD, c = idx - k * NPAD;
        float v = 0.f;
        if (c < 64)       v = W_ar[(size_t)k * 64 + c];
        else if (c == 64) v = W_f[k];
        else if (c < 130) v = W_r[(size_t)k * RCOLS + (c - 65)];
        g_W[idx] = v;
    } else {
        int e = idx - IN_ * NPAD;
        int j = e >> 6, k = e & 63;
        float v = 0.f;
        if (j < 65)       v = W_r[(size_t)(IN_ + k) * RCOLS + j];
        else if (j == 65) v = W_f[IN_ + k];
        __nv_bfloat16 h, l;
        split_bf16(v, h, l);
        int dst = j * 64 + (((k >> 3) ^ (j & 7)) << 3) + (k & 7);
        g_WBhi[dst] = h;
        g_WBlo[dst] = l;
    }
}

// W_o [K=2176][N=2048] -> g_B* [N][K] bf16 hi/lo (tiled transpose)
__global__ __launch_bounds__(256) void conv_B_kernel(const float* __restrict__ W_o)
{
    __shared__ float t[32][33];
    const int k0 = blockIdx.x * 32;
    const int n0 = blockIdx.y * 32;
    const int tid = threadIdx.x;
    #pragma unroll
    for (int p = 0; p < 4; p++) {
        int r = (tid >> 5) + p * 8, c = tid & 31;
        t[r][c] = W_o[(size_t)(k0 + r) * OUT_ + n0 + c];
    }
    __syncthreads();
    #pragma unroll
    for (int p = 0; p < 2; p++) {
        int r = (tid >> 4) + p * 16;
        int cc = (tid & 15) * 2;
        float v0 = t[cc][r], v1 = t[cc + 1][r];
        __nv_bfloat16 h0, l0, h1, l1;
        split_bf16(v0, h0, l0);
        split_bf16(v1, h1, l1);
        __nv_bfloat162 hp; hp.x = h0; hp.y = h1;
        __nv_bfloat162 lp; lp.x = l0; lp.y = l1;
        *(__nv_bfloat162*)(g_Bhi + (size_t)(n0 + r) * KO + k0 + cc) = hp;
        *(__nv_bfloat162*)(g_Blo + (size_t)(n0 + r) * KO + k0 + cc) = lp;
    }
}

// ==================================================================
// Kernel A: fused projections + x->bf16 hi/lo. GROUP=4, 2 CTAs/SM.
// ==================================================================
#define GROUP 4
#define CW4   33
#define KQ2   16
#define PTH   (CW4 * KQ2)         // 528
#define KSL   (IN_ / KQ2)         // 128

__global__ __launch_bounds__(PTH, 2) void proj_kernel(
    const float* __restrict__ x,
    const float* __restrict__ b_ar, const float* __restrict__ b_f,
    const float* __restrict__ b_r)
{
    extern __shared__ float psm[];
    float* xs  = psm;
    float* red = psm + GROUP * IN_;
    const int b0 = blockIdx.x * GROUP;

    for (int i = threadIdx.x; i < GROUP * (IN_ / 4); i += PTH) {
        int g = i >> 9, k4 = i & 511;
        ((float4*)(xs + g * IN_))[k4] =
            ((const float4*)(x + (size_t)(b0 + g) * IN_))[k4];
    }
    __syncthreads();

    for (int i = threadIdx.x; i < GROUP * (IN_ / 8); i += PTH) {
        int g = i >> 8, c8 = (i & 255) << 3;
        __nv_bfloat16 h[8], l[8];
        #pragma unroll
        for (int j = 0; j < 8; j++) split_bf16(xs[g * IN_ + c8 + j], h[j], l[j]);
        *(uint4*)(g_Ahi + (size_t)(b0 + g) * KO + c8) = *(const uint4*)h;
        *(uint4*)(g_Alo + (size_t)(b0 + g) * KO + c8) = *(const uint4*)l;
    }

    const int t  = threadIdx.x;
    const int c4 = t % CW4;
    const int kq = t / CW4;
    const int kbase = kq * KSL;

    float4 acc[GROUP];
    #pragma unroll
    for (int g = 0; g < GROUP; g++) acc[g] = make_float4(0.f, 0.f, 0.f, 0.f);

    const float4* wp = (const float4*)(g_W + (size_t)kbase * NPAD) + c4;
    #pragma unroll 8
    for (int k = 0; k < KSL; k++) {
        const float4 w = wp[(size_t)k * (NPAD / 4)];
        const int kk = kbase + k;
        #pragma unroll
        for (int g = 0; g < GROUP; g++) {
            const float xv = xs[g * IN_ + kk];
            acc[g].x = fmaf(xv, w.x, acc[g].x);
            acc[g].y = fmaf(xv, w.y, acc[g].y);
            acc[g].z = fmaf(xv, w.z, acc[g].z);
            acc[g].w = fmaf(xv, w.w, acc[g].w);
        }
    }
    #pragma unroll
    for (int g = 0; g < GROUP; g++)
        *(float4*)&red[(g * KQ2 + kq) * NPAD + c4 * 4] = acc[g];
    __syncthreads();

    if (t < 130) {
        float bias = (t < 64) ? b_ar[t] : (t == 64 ? b_f[0] : b_r[t - 65]);
        #pragma unroll
        for (int g = 0; g < GROUP; g++) {
            float s = bias;
            #pragma unroll
            for (int q = 0; q < KQ2; q++)
                s += red[(g * KQ2 + q) * NPAD + t];
            const int b = b0 + g;
            if (t < 64)       g_q[(size_t)b * MEM_ + t] = s;
            else if (t == 64) g_xf[b] = s;
            else              g_xr[(size_t)b * RCOLS + (t - 65)] = s;
        }
    }
}
#define PROJ_SMEM ((GROUP * IN_ + GROUP * KQ2 * NPAD) * 4)

// ==================================================================
// Kernel B: memory-fused (R10 version: fused load, resident hi+lo
// A-images, single MMA phase).
// ==================================================================
#define MTH   256
#define MSP   68
#define IMG_F    13312
#define TAIL_OFF (8704 + IMG_F)
#define MEM_SMEM ((TAIL_OFF + 1024) * 4)

__device__ __forceinline__ float blockReduce8(float v, float* red8, int isSum)
{
    #pragma unroll
    for (int o = 16; o; o >>= 1) {
        float u = __shfl_xor_sync(0xffffffffu, v, o);
        v = isSum ? (v + u) : fmaxf(v, u);
    }
    if ((threadIdx.x & 31) == 0) red8[threadIdx.x >> 5] = v;
    __syncthreads();
    float r = red8[0];
    #pragma unroll
    for (int i = 1; i < 8; i++) r = isSum ? (r + red8[i]) : fmaxf(r, red8[i]);
    __syncthreads();
    return r;
}

__global__ __launch_bounds__(MTH) void mem_kernel(
    const float* __restrict__ memory,
    const float* __restrict__ W_pr, const float* __restrict__ b_pr,
    float* __restrict__ new_memory)
{
    extern __shared__ float sm[];
    float* msf  = sm;
    char*  img  = (char*)(sm + 8704);
    float* remS = (float*)img;
    float* qs   = sm + TAIL_OFF;
    float* wpr  = qs + 64;
    float* xrs  = wpr + 64;
    float* s1   = xrs + 68;
    float* s2   = s1 + 128;
    float* red8 = s2 + 128;
    float* pad  = red8 + 8;

    const int b    = blockIdx.x;
    const int t    = threadIdx.x;
    const int wid  = t >> 5;
    const int lane = t & 31;
    const float* memb = memory + (size_t)b * NS * MEM_;
    const float xfv = g_xf[b];

    // ---- 1. fused load: gmem -> msf + Ahi/Alo swizzled images ----
    {
        __nv_bfloat16* Ah = (__nv_bfloat16*)img;
        __nv_bfloat16* Al = (__nv_bfloat16*)(img + 16384);
        for (int i8 = t; i8 < NS * MEM_ / 8; i8 += MTH) {
            const int e = i8 * 8;
            const int n = e >> 6, m = e & 63, q = m >> 3;
            float4 v0 = *(const float4*)(memb + e);
            float4 v1 = *(const float4*)(memb + e + 4);
            *(float4*)&msf[n * MSP + m]     = v0;
            *(float4*)&msf[n * MSP + m + 4] = v1;
            const float vv[8] = {v0.x, v0.y, v0.z, v0.w, v1.x, v1.y, v1.z, v1.w};
            __nv_bfloat16 h[8], l[8];
            #pragma unroll
            for (int j = 0; j < 8; j++) split_bf16(vv[j], h[j], l[j]);
            const int idx = n * 64 + ((q ^ (n & 7)) << 3);
            *(uint4*)(Ah + idx) = *(const uint4*)h;
            *(uint4*)(Al + idx) = *(const uint4*)l;
        }
    }
    {
        const uint4* wbh = (const uint4*)g_WBhi;
        const uint4* wbl = (const uint4*)g_WBlo;
        uint4* Bh = (uint4*)(img + 32768);
        uint4* Bl = (uint4*)(img + 43008);
        for (int i = t; i < 1280; i += MTH) {
            if (i < 640) Bh[i] = wbh[i];
            else         Bl[i - 640] = wbl[i - 640];
        }
    }
    if (t < 64) { qs[t] = g_q[(size_t)b * MEM_ + t]; wpr[t] = W_pr[t]; }
    if (t < 65) { xrs[t] = g_xr[(size_t)b * RCOLS + t]; }
    __syncthreads();

    // ---- 2. rem GEMM ----
    const uint32_t Abase = smem_u32(img);
    const uint32_t Bbase = Abase + 32768;
    const int rr   = wid * 16;
    const int lrow = ((lane >> 3) & 1) * 8 + (lane & 7);
    const int lh   = (lane >> 4) & 1;

    float c[10][4];
    #pragma unroll
    for (int i = 0; i < 10; i++)
        #pragma unroll
        for (int q = 0; q < 4; q++) c[i][q] = 0.f;

    #pragma unroll
    for (int s = 0; s < 4; s++) {
        const int hb = s * 2 + lh;
        const int arow = rr + lrow;
        const uint32_t aoff = arow * 128 + ((hb ^ (arow & 7)) << 4);
        uint32_t ah[4], al[4];
        ldm_x4(ah, Abase + aoff);
        ldm_x4(al, Abase + 16384 + aoff);
        #pragma unroll
        for (int gp = 0; gp < 5; gp++) {
            const int jr = gp * 16 + lrow;
            const uint32_t boff = jr * 128 + ((hb ^ (jr & 7)) << 4);
            uint32_t r4[4], q4[4];
            ldm_x4(r4, Bbase + boff);
            ldm_x4(q4, Bbase + 10240 + boff);
            uint32_t bh0[2] = {r4[0], r4[2]}, bh1[2] = {r4[1], r4[3]};
            uint32_t bl0[2] = {q4[0], q4[2]}, bl1[2] = {q4[1], q4[3]};
            mma16816(c[gp * 2], ah, bh0);
            mma16816(c[gp * 2], ah, bl0);
            mma16816(c[gp * 2], al, bh0);
            mma16816(c[gp * 2 + 1], ah, bh1);
            mma16816(c[gp * 2 + 1], ah, bl1);
            mma16816(c[gp * 2 + 1], al, bh1);
        }
    }
    __syncthreads();

    // ---- 3. phase 1: scores, softmax, recalls ----
    float s1v = -1e30f, s2v = -1e30f;
    if (t < NS) {
        float a = 0.f, p = 0.f;
        #pragma unroll
        for (int k4 = 0; k4 < 16; k4++) {
            float4 mv = *(float4*)&msf[t * MSP + k4 * 4];
            a = fmaf(mv.x, qs[k4 * 4 + 0], a);
            a = fmaf(mv.y, qs[k4 * 4 + 1], a);
            a = fmaf(mv.z, qs[k4 * 4 + 2], a);
            a = fmaf(mv.w, qs[k4 * 4 + 3], a);
            p = fmaf(mv.x, wpr[k4 * 4 + 0], p);
            p = fmaf(mv.y, wpr[k4 * 4 + 1], p);
            p = fmaf(mv.z, wpr[k4 * 4 + 2], p);
            p = fmaf(mv.w, wpr[k4 * 4 + 3], p);
        }
        s1v = a;
        s2v = p + b_pr[0];
    }
    float max1 = blockReduce8(s1v, red8, 0);
    float max2 = blockReduce8(s2v, red8, 0);
    float e1 = (t < NS) ? expf(s1v - max1) : 0.f;
    float e2 = (t < NS) ? expf(s2v - max2) : 0.f;
    float sum1 = blockReduce8(e1, red8, 1);
    float sum2 = blockReduce8(e2, red8, 1);
    if (t < NS) { s1[t] = e1 / sum1; s2[t] = e2 / sum2; }
    __syncthreads();

    {
        const int col = t & 63;
        const int grp = t >> 6;
        float act = 0.f, pas = 0.f;
        #pragma unroll 4
        for (int n = grp * 32; n < grp * 32 + 32; n++) {
            float mv = msf[n * MSP + col];
            act = fmaf(s1[n], mv, act);
            pas = fmaf(s2[n], mv, pas);
        }
        pad[grp * 64 + col]       = act;
        pad[256 + grp * 64 + col] = pas;
    }
    __syncthreads();
    if (t < MEM_) {
        float act = pad[t] + pad[64 + t] + pad[128 + t] + pad[192 + t];
        float pas = pad[256 + t] + pad[320 + t] + pad[384 + t] + pad[448 + t];
        __nv_bfloat16 h, l;
        split_bf16(act, h, l);
        g_Ahi[(size_t)b * KO + IN_ + t] = h;
        g_Alo[(size_t)b * KO + IN_ + t] = l;
        split_bf16(pas, h, l);
        g_Ahi[(size_t)b * KO + IN_ + MEM_ + t] = h;
        g_Alo[(size_t)b * KO + IN_ + MEM_ + t] = l;
    }
    __syncthreads();

    // ---- 4. rem frags (+bias, sigmoid col 65) -> remS ----
    {
        const int g  = lane >> 2;
        const int tg = lane & 3;
        const int r0 = rr + g;
        #pragma unroll
        for (int nf = 0; nf < 10; nf++) {
            const int col = nf * 8 + tg * 2;
            #pragma unroll
            for (int half = 0; half < 2; half++) {
                const int cc = col + half;
                if (cc > 65) continue;
                const float bias = (cc < 65) ? xrs[cc] : 0.f;
                float v0 = c[nf][half]     + bias;
                float v1 = c[nf][half + 2] + bias;
                if (cc == 65) {
                    v0 = 1.1f / (1.f + expf(-(v0 + xfv)));
                    v1 = 1.1f / (1.f + expf(-(v1 + xfv)));
                }
                remS[r0 * 72 + cc]       = v0;
                remS[(r0 + 8) * 72 + cc] = v1;
            }
        }
    }
    __syncthreads();

    // ---- 5. gating ----
    float* nm = new_memory + (size_t)b * NS * MEM_;
    for (int i4 = t; i4 < NS * MEM_ / 4; i4 += MTH) {
        int e = i4 * 4;
        int n = e >> 6, m = e & 63;
        const float f    = remS[n * 72 + 65];
        const float gate = remS[n * 72 + 64];
        float4 mv = *(float4*)&msf[n * MSP + m];
        float4 rv = *(float4*)&remS[n * 72 + m];
        float4 o;
        o.x = fmaf(mv.x, f, gate * rv.x);
        o.y = fmaf(mv.y, f, gate * rv.y);
        o.z = fmaf(mv.z, f, gate * rv.z);
        o.w = fmaf(mv.w, f, gate * rv.w);
        *(float4*)(nm + e) = o;
    }
}

// ==================================================================
// Kernel C: mma.sync bf16-split GEMM over k in [0, 2048), 4-stage
// ring. Overlaps with mem_kernel (doesn't touch act/pas columns).
// ==================================================================
#define CTA_M   64
#define CTA_N   128
#define KCHUNK  32
#define NKC_MAIN 64                       // k < 2048
#define A_TB    4096
#define B_TB    8192
#define STAGE_B (2 * A_TB + 2 * B_TB)     // 24576
#define GEMM_SMEM (4 * STAGE_B)           // 98304

__device__ __forceinline__ uint32_t swz64(int r, int h) {
    return (uint32_t)((h ^ (r & 3) ^ ((r >> 2) & 1)) << 4);
}

__device__ __forceinline__ void gemm_prefetch(
    uint32_t smem, int tid, int br, int bc, int k0, int stage)
{
    const uint32_t sb = smem + stage * STAGE_B;
    #pragma unroll
    for (int q = 0; q < 2; q++) {
        int u = tid + q * 256;
        int tile = u >> 8, rm = u & 255;
        int r = rm >> 2, h = rm & 3;
        const __nv_bfloat16* src =
            (tile ? g_Alo : g_Ahi) + (size_t)(br + r) * KO + k0 + h * 8;
        cp16(sb + tile * A_TB + r * 64 + swz64(r, h), src);
    }
    #pragma unroll
    for (int q = 0; q < 4; q++) {
        int u = tid + q * 256;
        int tile = u >> 9, rm = u & 511;
        int n = rm >> 2, h = rm & 3;
        const __nv_bfloat16* src =
            (tile ? g_Blo : g_Bhi) + (size_t)(bc + n) * KO + k0 + h * 8;
        cp16(sb + 2 * A_TB + tile * B_TB + n * 64 + swz64(n, h), src);
    }
    CP_COMMIT();
}

__device__ __forceinline__ void gemm_chunk(
    uint32_t sb, int wm, int wn, int lrow, int lh, float c[2][4][4])
{
    #pragma unroll
    for (int s = 0; s < 2; s++) {
        const int h = s * 2 + lh;
        uint32_t ah[2][4], al[2][4];
        #pragma unroll
        for (int f = 0; f < 2; f++) {
            int rr = wm * 32 + f * 16 + lrow;
            ldm_x4(ah[f], sb + rr * 64 + swz64(rr, h));
            ldm_x4(al[f], sb + A_TB + rr * 64 + swz64(rr, h));
        }
        uint32_t bh[4][2], bl[4][2];
        #pragma unroll
        for (int jj = 0; jj < 2; jj++) {
            int nn = wn * 32 + jj * 16 + lrow;
            uint32_t r4[4];
            ldm_x4(r4, sb + 2 * A_TB + nn * 64 + swz64(nn, h));
            bh[2 * jj][0] = r4[0]; bh[2 * jj + 1][0] = r4[1];
            bh[2 * jj][1] = r4[2]; bh[2 * jj + 1][1] = r4[3];
            ldm_x4(r4, sb + 2 * A_TB + B_TB + nn * 64 + swz64(nn, h));
            bl[2 * jj][0] = r4[0]; bl[2 * jj + 1][0] = r4[1];
            bl[2 * jj][1] = r4[2]; bl[2 * jj + 1][1] = r4[3];
        }
        #pragma unroll
        for (int mf = 0; mf < 2; mf++)
            #pragma unroll
            for (int nf = 0; nf < 4; nf++) {
                mma16816(c[mf][nf], ah[mf], bh[nf]);
                mma16816(c[mf][nf], ah[mf], bl[nf]);
                mma16816(c[mf][nf], al[mf], bh[nf]);
            }
    }
}

__global__ __launch_bounds__(256, 2) void out_gemm_main(
    const float* __restrict__ b_o, float* __restrict__ out)
{
    extern __shared__ __align__(128) char gsm[];
    const int tid  = threadIdx.x;
    const int wid  = tid >> 5;
    const int lane = tid & 31;
    const int wm   = wid & 1;
    const int wn   = wid >> 1;
    const int br   = blockIdx.y * CTA_M;
    const int bc   = blockIdx.x * CTA_N;
    const uint32_t smem = smem_u32(gsm);

    float c[2][4][4];
    #pragma unroll
    for (int i = 0; i < 2; i++)
        #pragma unroll
        for (int j = 0; j < 4; j++)
            #pragma unroll
            for (int q = 0; q < 4; q++) c[i][j][q] = 0.f;

    const int lrow = ((lane >> 3) & 1) * 8 + (lane & 7);
    const int lh   = (lane >> 4) & 1;

    gemm_prefetch(smem, tid, br, bc, 0 * KCHUNK, 0);
    gemm_prefetch(smem, tid, br, bc, 1 * KCHUNK, 1);
    gemm_prefetch(smem, tid, br, bc, 2 * KCHUNK, 2);

    for (int kc = 0; kc < NKC_MAIN; kc++) {
        if (kc + 3 < NKC_MAIN)      { gemm_prefetch(smem, tid, br, bc, (kc + 3) * KCHUNK, (kc + 3) & 3); CP_WAIT(3); }
        else if (kc + 2 < NKC_MAIN) { CP_WAIT(2); }
        else if (kc + 1 < NKC_MAIN) { CP_WAIT(1); }
        else                        { CP_WAIT(0); }
        __syncthreads();
        gemm_chunk(smem + (kc & 3) * STAGE_B, wm, wn, lrow, lh, c);
        __syncthreads();
    }

    const int g  = lane >> 2;
    const int tg = lane & 3;
    #pragma unroll
    for (int nf = 0; nf < 4; nf++) {
        const int col = bc + wn * 32 + nf * 8 + tg * 2;
        const float2 bb = *(const float2*)(b_o + col);
        #pragma unroll
        for (int mf = 0; mf < 2; mf++) {
            const int row0 = br + wm * 32 + mf * 16 + g;
            float2 v0 = make_float2(c[mf][nf][0] + bb.x, c[mf][nf][1] + bb.y);
            float2 v1 = make_float2(c[mf][nf][2] + bb.x, c[mf][nf][3] + bb.y);
            *(float2*)(out + (size_t)row0 * OUT_ + col)       = v0;
            *(float2*)(out + (size_t)(row0 + 8) * OUT_ + col) = v1;
        }
    }
}

// Tail: out += A[:, 2048:2176] @ B[:, 2048:2176]^T   (4 k-chunks)
__global__ __launch_bounds__(256, 2) void out_gemm_tail(float* __restrict__ out)
{
    extern __shared__ __align__(128) char gsm[];
    const int tid  = threadIdx.x;
    const int wid  = tid >> 5;
    const int lane = tid & 31;
    const int wm   = wid & 1;
    const int wn   = wid >> 1;
    const int br   = blockIdx.y * CTA_M;
    const int bc   = blockIdx.x * CTA_N;
    const uint32_t smem = smem_u32(gsm);

    float c[2][4][4];
    #pragma unroll
    for (int i = 0; i < 2; i++)
        #pragma unroll
        for (int j = 0; j < 4; j++)
            #pragma unroll
            for (int q = 0; q < 4; q++) c[i][j][q] = 0.f;

    const int lrow = ((lane >> 3) & 1) * 8 + (lane & 7);
    const int lh   = (lane >> 4) & 1;

    #pragma unroll
    for (int kc = 0; kc < 4; kc++)
        gemm_prefetch(smem, tid, br, bc, IN_ + kc * KCHUNK, kc);
    CP_WAIT(0);
    __syncthreads();

    #pragma unroll
    for (int kc = 0; kc < 4; kc++)
        gemm_chunk(smem + kc * STAGE_B, wm, wn, lrow, lh, c);

    const int g  = lane >> 2;
    const int tg = lane & 3;
    #pragma unroll
    for (int nf = 0; nf < 4; nf++) {
        const int col = bc + wn * 32 + nf * 8 + tg * 2;
        #pragma unroll
        for (int mf = 0; mf < 2; mf++) {
            const int row0 = br + wm * 32 + mf * 16 + g;
            float2 o0 = *(const float2*)(out + (size_t)row0 * OUT_ + col);
            float2 o1 = *(const float2*)(out + (size_t)(row0 + 8) * OUT_ + col);
            o0.x += c[mf][nf][0]; o0.y += c[mf][nf][1];
            o1.x += c[mf][nf][2]; o1.y += c[mf][nf][3];
            *(float2*)(out + (size_t)row0 * OUT_ + col)       = o0;
            *(float2*)(out + (size_t)(row0 + 8) * OUT_ + col) = o1;
        }
    }
}

// ==================================================================
// Launch: conv_B ∥ (pack→proj) ; then gemm_main ∥ mem ; then tail.
// ==================================================================
extern "C" void kernel_launch(void* const* d_in, const int* in_sizes, int n_in,
                              void* d_out, int out_size)
{
    const float* x    = (const float*)d_in[0];
    const float* mem  = (const float*)d_in[1];
    const float* W_ar = (const float*)d_in[2];
    const float* b_ar = (const float*)d_in[3];
    const float* W_pr = (const float*)d_in[4];
    const float* b_pr = (const float*)d_in[5];
    const float* W_f  = (const float*)d_in[6];
    const float* b_f  = (const float*)d_in[7];
    const float* W_r  = (const float*)d_in[8];
    const float* b_r  = (const float*)d_in[9];
    const float* W_o  = (const float*)d_in[10];
    const float* b_o  = (const float*)d_in[11];

    float* out     = (float*)d_out;
    float* new_mem = out + (size_t)B_ * OUT_;

    static cudaStream_t s1 = nullptr, s2 = nullptr;
    static cudaEvent_t ev_root = nullptr, ev_convB = nullptr,
                       ev_proj = nullptr, ev_gmain = nullptr;
    if (!s1) {
        cudaStreamCreateWithFlags(&s1, cudaStreamNonBlocking);
        cudaStreamCreateWithFlags(&s2, cudaStreamNonBlocking);
        cudaEventCreateWithFlags(&ev_root, cudaEventDisableTiming);
        cudaEventCreateWithFlags(&ev_convB, cudaEventDisableTiming);
        cudaEventCreateWithFlags(&ev_proj, cudaEventDisableTiming);
        cudaEventCreateWithFlags(&ev_gmain, cudaEventDisableTiming);
        cudaFuncSetAttribute(mem_kernel, cudaFuncAttributeMaxDynamicSharedMemorySize, MEM_SMEM);
        cudaFuncSetAttribute(proj_kernel, cudaFuncAttributeMaxDynamicSharedMemorySize, PROJ_SMEM);
        cudaFuncSetAttribute(out_gemm_main, cudaFuncAttributeMaxDynamicSharedMemorySize, GEMM_SMEM);
        cudaFuncSetAttribute(out_gemm_tail, cudaFuncAttributeMaxDynamicSharedMemorySize, GEMM_SMEM);
    }

    // fork: conv_B on s1
    cudaEventRecord(ev_root, 0);
    cudaStreamWaitEvent(s1, ev_root, 0);
    {
        dim3 g(KO / 32, OUT_ / 32);
        conv_B_kernel<<<g, 256, 0, s1>>>(W_o);
    }
    cudaEventRecord(ev_convB, s1);

    // main chain: pack -> proj
    pack_kernel<<<(PACK_TOT + 255) / 256, 256>>>(W_ar, W_f, W_r);
    proj_kernel<<<B_ / GROUP, PTH, PROJ_SMEM>>>(x, b_ar, b_f, b_r);
    cudaEventRecord(ev_proj, 0);

    // s2: gemm_main (needs proj's x-conversion + conv_B)
    cudaStreamWaitEvent(s2, ev_proj, 0);
    cudaStreamWaitEvent(s2, ev_convB, 0);
    {
        dim3 g(OUT_ / CTA_N, B_ / CTA_M);   // (16, 8)
        out_gemm_main<<<g, 256, GEMM_SMEM, s2>>>(b_o, out);
    }
    cudaEventRecord(ev_gmain, s2);

    // main: mem_kernel (concurrent with gemm_main)
    mem_kernel<<<B_, MTH, MEM_SMEM>>>(mem, W_pr, b_pr, new_mem);

    // main: tail (needs mem's act/pas + gemm_main's out)
    cudaStreamWaitEvent(0, ev_gmain, 0);
    {
        dim3 g(OUT_ / CTA_N, B_ / CTA_M);
        out_gemm_tail<<<g, 256, GEMM_SMEM>>>(out);
    }
}

// round 13
// speedup vs baseline: 1.3237x; 1.3237x over previous
#include <cuda_runtime.h>
#include <cuda_bf16.h>
#include <math.h>
#include <cstdint>

// Problem constants
#define B_    512
#define NS    128
#define IN_   2048
#define MEM_  64
#define OUT_  2048
#define RCOLS 65
#define KO    2176          // IN_ + 2*MEM_
#define NPAD  132

// ------------------------------------------------------------------
// Scratch (device globals)
// ------------------------------------------------------------------
__device__ float g_q  [B_ * MEM_];
__device__ float g_xf [B_];
__device__ float g_xr [B_ * RCOLS];
__device__ float g_W  [IN_ * NPAD];
__device__ __nv_bfloat16 g_Ahi[B_ * KO];       // [512][2176]  (x | act | pas)
__device__ __nv_bfloat16 g_Alo[B_ * KO];
__device__ __nv_bfloat16 g_Bhi[OUT_ * KO];     // [2048][2176] = W_o^T
__device__ __nv_bfloat16 g_Blo[OUT_ * KO];
__device__ __nv_bfloat16 g_WBhi[80 * 64];
__device__ __nv_bfloat16 g_WBlo[80 * 64];

// ------------------------------------------------------------------
// Helpers
// ------------------------------------------------------------------
__device__ __forceinline__ uint32_t smem_u32(const void* p) {
    uint32_t a;
    asm("{ .reg .u64 t; cvta.to.shared.u64 t, %1; cvt.u32.u64 %0, t; }"
        : "=r"(a) : "l"(p));
    return a;
}
__device__ __forceinline__ void cp16(uint32_t dst, const void* src) {
    asm volatile("cp.async.cg.shared.global [%0], [%1], 16;" :: "r"(dst), "l"(src));
}
#define CP_COMMIT()  asm volatile("cp.async.commit_group;" ::: "memory")
#define CP_WAIT(n)   asm volatile("cp.async.wait_group %0;" :: "n"(n) : "memory")

__device__ __forceinline__ void ldm_x4(uint32_t* r, uint32_t addr) {
    asm volatile("ldmatrix.sync.aligned.m8n8.x4.shared.b16 {%0,%1,%2,%3}, [%4];"
        : "=r"(r[0]), "=r"(r[1]), "=r"(r[2]), "=r"(r[3]) : "r"(addr));
}
__device__ __forceinline__ void mma16816(float* c, const uint32_t* a, const uint32_t* b) {
    asm volatile(
        "mma.sync.aligned.m16n8k16.row.col.f32.bf16.bf16.f32 "
        "{%0,%1,%2,%3}, {%4,%5,%6,%7}, {%8,%9}, {%0,%1,%2,%3};"
        : "+f"(c[0]), "+f"(c[1]), "+f"(c[2]), "+f"(c[3])
        : "r"(a[0]), "r"(a[1]), "r"(a[2]), "r"(a[3]), "r"(b[0]), "r"(b[1]));
}
__device__ __forceinline__ void split_bf16(float v, __nv_bfloat16& h, __nv_bfloat16& l) {
    h = __float2bfloat16(v);
    l = __float2bfloat16(v - __bfloat162float(h));
}

// ==================================================================
// Prep kernels
// ==================================================================
#define PACK_TOT (IN_ * NPAD + 80 * 64)
__global__ __launch_bounds__(256) void pack_kernel(
    const float* __restrict__ W_ar, const float* __restrict__ W_f,
    const float* __restrict__ W_r)
{
    int idx = blockIdx.x * 256 + threadIdx.x;
    if (idx >= PACK_TOT) return;
    if (idx < IN_ * NPAD) {
        int k = idx / NPAD, c = idx - k * NPAD;
        float v = 0.f;
        if (c < 64)       v = W_ar[(size_t)k * 64 + c];
        else if (c == 64) v = W_f[k];
        else if (c < 130) v = W_r[(size_t)k * RCOLS + (c - 65)];
        g_W[idx] = v;
    } else {
        int e = idx - IN_ * NPAD;
        int j = e >> 6, k = e & 63;
        float v = 0.f;
        if (j < 65)       v = W_r[(size_t)(IN_ + k) * RCOLS + j];
        else if (j == 65) v = W_f[IN_ + k];
        __nv_bfloat16 h, l;
        split_bf16(v, h, l);
        int dst = j * 64 + (((k >> 3) ^ (j & 7)) << 3) + (k & 7);
        g_WBhi[dst] = h;
        g_WBlo[dst] = l;
    }
}

// W_o [K=2176][N=2048] -> g_B* [N][K] bf16 hi/lo (tiled transpose)
__global__ __launch_bounds__(256) void conv_B_kernel(const float* __restrict__ W_o)
{
    __shared__ float t[32][33];
    const int k0 = blockIdx.x * 32;
    const int n0 = blockIdx.y * 32;
    const int tid = threadIdx.x;
    #pragma unroll
    for (int p = 0; p < 4; p++) {
        int r = (tid >> 5) + p * 8, c = tid & 31;
        t[r][c] = W_o[(size_t)(k0 + r) * OUT_ + n0 + c];
    }
    __syncthreads();
    #pragma unroll
    for (int p = 0; p < 2; p++) {
        int r = (tid >> 4) + p * 16;
        int cc = (tid & 15) * 2;
        float v0 = t[cc][r], v1 = t[cc + 1][r];
        __nv_bfloat16 h0, l0, h1, l1;
        split_bf16(v0, h0, l0);
        split_bf16(v1, h1, l1);
        __nv_bfloat162 hp; hp.x = h0; hp.y = h1;
        __nv_bfloat162 lp; lp.x = l0; lp.y = l1;
        *(__nv_bfloat162*)(g_Bhi + (size_t)(n0 + r) * KO + k0 + cc) = hp;
        *(__nv_bfloat162*)(g_Blo + (size_t)(n0 + r) * KO + k0 + cc) = lp;
    }
}

// ==================================================================
// Kernel A: fused projections + x->bf16 hi/lo. GROUP=4, 2 CTAs/SM.
// ==================================================================
#define GROUP 4
#define CW4   33
#define KQ2   16
#define PTH   (CW4 * KQ2)         // 528
#define KSL   (IN_ / KQ2)         // 128

__global__ __launch_bounds__(PTH, 2) void proj_kernel(
    const float* __restrict__ x,
    const float* __restrict__ b_ar, const float* __restrict__ b_f,
    const float* __restrict__ b_r)
{
    extern __shared__ float psm[];
    float* xs  = psm;
    float* red = psm + GROUP * IN_;
    const int b0 = blockIdx.x * GROUP;

    for (int i = threadIdx.x; i < GROUP * (IN_ / 4); i += PTH) {
        int g = i >> 9, k4 = i & 511;
        ((float4*)(xs + g * IN_))[k4] =
            ((const float4*)(x + (size_t)(b0 + g) * IN_))[k4];
    }
    __syncthreads();

    for (int i = threadIdx.x; i < GROUP * (IN_ / 8); i += PTH) {
        int g = i >> 8, c8 = (i & 255) << 3;
        __nv_bfloat16 h[8], l[8];
        #pragma unroll
        for (int j = 0; j < 8; j++) split_bf16(xs[g * IN_ + c8 + j], h[j], l[j]);
        *(uint4*)(g_Ahi + (size_t)(b0 + g) * KO + c8) = *(const uint4*)h;
        *(uint4*)(g_Alo + (size_t)(b0 + g) * KO + c8) = *(const uint4*)l;
    }

    const int t  = threadIdx.x;
    const int c4 = t % CW4;
    const int kq = t / CW4;
    const int kbase = kq * KSL;

    float4 acc[GROUP];
    #pragma unroll
    for (int g = 0; g < GROUP; g++) acc[g] = make_float4(0.f, 0.f, 0.f, 0.f);

    const float4* wp = (const float4*)(g_W + (size_t)kbase * NPAD) + c4;
    #pragma unroll 8
    for (int k = 0; k < KSL; k++) {
        const float4 w = wp[(size_t)k * (NPAD / 4)];
        const int kk = kbase + k;
        #pragma unroll
        for (int g = 0; g < GROUP; g++) {
            const float xv = xs[g * IN_ + kk];
            acc[g].x = fmaf(xv, w.x, acc[g].x);
            acc[g].y = fmaf(xv, w.y, acc[g].y);
            acc[g].z = fmaf(xv, w.z, acc[g].z);
            acc[g].w = fmaf(xv, w.w, acc[g].w);
        }
    }
    #pragma unroll
    for (int g = 0; g < GROUP; g++)
        *(float4*)&red[(g * KQ2 + kq) * NPAD + c4 * 4] = acc[g];
    __syncthreads();

    if (t < 130) {
        float bias = (t < 64) ? b_ar[t] : (t == 64 ? b_f[0] : b_r[t - 65]);
        #pragma unroll
        for (int g = 0; g < GROUP; g++) {
            float s = bias;
            #pragma unroll
            for (int q = 0; q < KQ2; q++)
                s += red[(g * KQ2 + q) * NPAD + t];
            const int b = b0 + g;
            if (t < 64)       g_q[(size_t)b * MEM_ + t] = s;
            else if (t == 64) g_xf[b] = s;
            else              g_xr[(size_t)b * RCOLS + (t - 65)] = s;
        }
    }
}
#define PROJ_SMEM ((GROUP * IN_ + GROUP * KQ2 * NPAD) * 4)

// ==================================================================
// Kernel B: memory-fused (R10 version).
// ==================================================================
#define MTH   256
#define MSP   68
#define IMG_F    13312
#define TAIL_OFF (8704 + IMG_F)
#define MEM_SMEM ((TAIL_OFF + 1024) * 4)

__device__ __forceinline__ float blockReduce8(float v, float* red8, int isSum)
{
    #pragma unroll
    for (int o = 16; o; o >>= 1) {
        float u = __shfl_xor_sync(0xffffffffu, v, o);
        v = isSum ? (v + u) : fmaxf(v, u);
    }
    if ((threadIdx.x & 31) == 0) red8[threadIdx.x >> 5] = v;
    __syncthreads();
    float r = red8[0];
    #pragma unroll
    for (int i = 1; i < 8; i++) r = isSum ? (r + red8[i]) : fmaxf(r, red8[i]);
    __syncthreads();
    return r;
}

__global__ __launch_bounds__(MTH) void mem_kernel(
    const float* __restrict__ memory,
    const float* __restrict__ W_pr, const float* __restrict__ b_pr,
    float* __restrict__ new_memory)
{
    extern __shared__ float sm[];
    float* msf  = sm;
    char*  img  = (char*)(sm + 8704);
    float* remS = (float*)img;
    float* qs   = sm + TAIL_OFF;
    float* wpr  = qs + 64;
    float* xrs  = wpr + 64;
    float* s1   = xrs + 68;
    float* s2   = s1 + 128;
    float* red8 = s2 + 128;
    float* pad  = red8 + 8;

    const int b    = blockIdx.x;
    const int t    = threadIdx.x;
    const int wid  = t >> 5;
    const int lane = t & 31;
    const float* memb = memory + (size_t)b * NS * MEM_;
    const float xfv = g_xf[b];

    {
        __nv_bfloat16* Ah = (__nv_bfloat16*)img;
        __nv_bfloat16* Al = (__nv_bfloat16*)(img + 16384);
        for (int i8 = t; i8 < NS * MEM_ / 8; i8 += MTH) {
            const int e = i8 * 8;
            const int n = e >> 6, m = e & 63, q = m >> 3;
            float4 v0 = *(const float4*)(memb + e);
            float4 v1 = *(const float4*)(memb + e + 4);
            *(float4*)&msf[n * MSP + m]     = v0;
            *(float4*)&msf[n * MSP + m + 4] = v1;
            const float vv[8] = {v0.x, v0.y, v0.z, v0.w, v1.x, v1.y, v1.z, v1.w};
            __nv_bfloat16 h[8], l[8];
            #pragma unroll
            for (int j = 0; j < 8; j++) split_bf16(vv[j], h[j], l[j]);
            const int idx = n * 64 + ((q ^ (n & 7)) << 3);
            *(uint4*)(Ah + idx) = *(const uint4*)h;
            *(uint4*)(Al + idx) = *(const uint4*)l;
        }
    }
    {
        const uint4* wbh = (const uint4*)g_WBhi;
        const uint4* wbl = (const uint4*)g_WBlo;
        uint4* Bh = (uint4*)(img + 32768);
        uint4* Bl = (uint4*)(img + 43008);
        for (int i = t; i < 1280; i += MTH) {
            if (i < 640) Bh[i] = wbh[i];
            else         Bl[i - 640] = wbl[i - 640];
        }
    }
    if (t < 64) { qs[t] = g_q[(size_t)b * MEM_ + t]; wpr[t] = W_pr[t]; }
    if (t < 65) { xrs[t] = g_xr[(size_t)b * RCOLS + t]; }
    __syncthreads();

    const uint32_t Abase = smem_u32(img);
    const uint32_t Bbase = Abase + 32768;
    const int rr   = wid * 16;
    const int lrow = ((lane >> 3) & 1) * 8 + (lane & 7);
    const int lh   = (lane >> 4) & 1;

    float c[10][4];
    #pragma unroll
    for (int i = 0; i < 10; i++)
        #pragma unroll
        for (int q = 0; q < 4; q++) c[i][q] = 0.f;

    #pragma unroll
    for (int s = 0; s < 4; s++) {
        const int hb = s * 2 + lh;
        const int arow = rr + lrow;
        const uint32_t aoff = arow * 128 + ((hb ^ (arow & 7)) << 4);
        uint32_t ah[4], al[4];
        ldm_x4(ah, Abase + aoff);
        ldm_x4(al, Abase + 16384 + aoff);
        #pragma unroll
        for (int gp = 0; gp < 5; gp++) {
            const int jr = gp * 16 + lrow;
            const uint32_t boff = jr * 128 + ((hb ^ (jr & 7)) << 4);
            uint32_t r4[4], q4[4];
            ldm_x4(r4, Bbase + boff);
            ldm_x4(q4, Bbase + 10240 + boff);
            uint32_t bh0[2] = {r4[0], r4[2]}, bh1[2] = {r4[1], r4[3]};
            uint32_t bl0[2] = {q4[0], q4[2]}, bl1[2] = {q4[1], q4[3]};
            mma16816(c[gp * 2], ah, bh0);
            mma16816(c[gp * 2], ah, bl0);
            mma16816(c[gp * 2], al, bh0);
            mma16816(c[gp * 2 + 1], ah, bh1);
            mma16816(c[gp * 2 + 1], ah, bl1);
            mma16816(c[gp * 2 + 1], al, bh1);
        }
    }
    __syncthreads();

    float s1v = -1e30f, s2v = -1e30f;
    if (t < NS) {
        float a = 0.f, p = 0.f;
        #pragma unroll
        for (int k4 = 0; k4 < 16; k4++) {
            float4 mv = *(float4*)&msf[t * MSP + k4 * 4];
            a = fmaf(mv.x, qs[k4 * 4 + 0], a);
            a = fmaf(mv.y, qs[k4 * 4 + 1], a);
            a = fmaf(mv.z, qs[k4 * 4 + 2], a);
            a = fmaf(mv.w, qs[k4 * 4 + 3], a);
            p = fmaf(mv.x, wpr[k4 * 4 + 0], p);
            p = fmaf(mv.y, wpr[k4 * 4 + 1], p);
            p = fmaf(mv.z, wpr[k4 * 4 + 2], p);
            p = fmaf(mv.w, wpr[k4 * 4 + 3], p);
        }
        s1v = a;
        s2v = p + b_pr[0];
    }
    float max1 = blockReduce8(s1v, red8, 0);
    float max2 = blockReduce8(s2v, red8, 0);
    float e1 = (t < NS) ? expf(s1v - max1) : 0.f;
    float e2 = (t < NS) ? expf(s2v - max2) : 0.f;
    float sum1 = blockReduce8(e1, red8, 1);
    float sum2 = blockReduce8(e2, red8, 1);
    if (t < NS) { s1[t] = e1 / sum1; s2[t] = e2 / sum2; }
    __syncthreads();

    {
        const int col = t & 63;
        const int grp = t >> 6;
        float act = 0.f, pas = 0.f;
        #pragma unroll 4
        for (int n = grp * 32; n < grp * 32 + 32; n++) {
            float mv = msf[n * MSP + col];
            act = fmaf(s1[n], mv, act);
            pas = fmaf(s2[n], mv, pas);
        }
        pad[grp * 64 + col]       = act;
        pad[256 + grp * 64 + col] = pas;
    }
    __syncthreads();
    if (t < MEM_) {
        float act = pad[t] + pad[64 + t] + pad[128 + t] + pad[192 + t];
        float pas = pad[256 + t] + pad[320 + t] + pad[384 + t] + pad[448 + t];
        __nv_bfloat16 h, l;
        split_bf16(act, h, l);
        g_Ahi[(size_t)b * KO + IN_ + t] = h;
        g_Alo[(size_t)b * KO + IN_ + t] = l;
        split_bf16(pas, h, l);
        g_Ahi[(size_t)b * KO + IN_ + MEM_ + t] = h;
        g_Alo[(size_t)b * KO + IN_ + MEM_ + t] = l;
    }
    __syncthreads();

    {
        const int g  = lane >> 2;
        const int tg = lane & 3;
        const int r0 = rr + g;
        #pragma unroll
        for (int nf = 0; nf < 10; nf++) {
            const int col = nf * 8 + tg * 2;
            #pragma unroll
            for (int half = 0; half < 2; half++) {
                const int cc = col + half;
                if (cc > 65) continue;
                const float bias = (cc < 65) ? xrs[cc] : 0.f;
                float v0 = c[nf][half]     + bias;
                float v1 = c[nf][half + 2] + bias;
                if (cc == 65) {
                    v0 = 1.1f / (1.f + expf(-(v0 + xfv)));
                    v1 = 1.1f / (1.f + expf(-(v1 + xfv)));
                }
                remS[r0 * 72 + cc]       = v0;
                remS[(r0 + 8) * 72 + cc] = v1;
            }
        }
    }
    __syncthreads();

    float* nm = new_memory + (size_t)b * NS * MEM_;
    for (int i4 = t; i4 < NS * MEM_ / 4; i4 += MTH) {
        int e = i4 * 4;
        int n = e >> 6, m = e & 63;
        const float f    = remS[n * 72 + 65];
        const float gate = remS[n * 72 + 64];
        float4 mv = *(float4*)&msf[n * MSP + m];
        float4 rv = *(float4*)&remS[n * 72 + m];
        float4 o;
        o.x = fmaf(mv.x, f, gate * rv.x);
        o.y = fmaf(mv.y, f, gate * rv.y);
        o.z = fmaf(mv.z, f, gate * rv.z);
        o.w = fmaf(mv.w, f, gate * rv.w);
        *(float4*)(nm + e) = o;
    }
}

// ==================================================================
// Kernel C: mma.sync bf16-split GEMM over all 68 chunks.
// 4-stage ring, prefetch distance 2, ONE __syncthreads per chunk.
// Safety: at the top-of-iter barrier all warps finished chunk kc-1;
// prefetch writes stage (kc+2)&3 which differs from the stages read
// by chunks kc and kc+1, and its previous reader (chunk kc-2)
// completed at least two barriers ago.
// ==================================================================
#define CTA_M   64
#define CTA_N   128
#define KCHUNK  32
#define NKC     68
#define A_TB    4096
#define B_TB    8192
#define STAGE_B (2 * A_TB + 2 * B_TB)     // 24576
#define GEMM_SMEM (4 * STAGE_B)           // 98304

__device__ __forceinline__ uint32_t swz64(int r, int h) {
    return (uint32_t)((h ^ (r & 3) ^ ((r >> 2) & 1)) << 4);
}

__device__ __forceinline__ void gemm_prefetch(
    uint32_t smem, int tid, int br, int bc, int k0, int stage)
{
    const uint32_t sb = smem + stage * STAGE_B;
    #pragma unroll
    for (int q = 0; q < 2; q++) {
        int u = tid + q * 256;
        int tile = u >> 8, rm = u & 255;
        int r = rm >> 2, h = rm & 3;
        const __nv_bfloat16* src =
            (tile ? g_Alo : g_Ahi) + (size_t)(br + r) * KO + k0 + h * 8;
        cp16(sb + tile * A_TB + r * 64 + swz64(r, h), src);
    }
    #pragma unroll
    for (int q = 0; q < 4; q++) {
        int u = tid + q * 256;
        int tile = u >> 9, rm = u & 511;
        int n = rm >> 2, h = rm & 3;
        const __nv_bfloat16* src =
            (tile ? g_Blo : g_Bhi) + (size_t)(bc + n) * KO + k0 + h * 8;
        cp16(sb + 2 * A_TB + tile * B_TB + n * 64 + swz64(n, h), src);
    }
    CP_COMMIT();
}

__device__ __forceinline__ void gemm_chunk(
    uint32_t sb, int wm, int wn, int lrow, int lh, float c[2][4][4])
{
    #pragma unroll
    for (int s = 0; s < 2; s++) {
        const int h = s * 2 + lh;
        uint32_t ah[2][4], al[2][4];
        #pragma unroll
        for (int f = 0; f < 2; f++) {
            int rr = wm * 32 + f * 16 + lrow;
            ldm_x4(ah[f], sb + rr * 64 + swz64(rr, h));
            ldm_x4(al[f], sb + A_TB + rr * 64 + swz64(rr, h));
        }
        uint32_t bh[4][2], bl[4][2];
        #pragma unroll
        for (int jj = 0; jj < 2; jj++) {
            int nn = wn * 32 + jj * 16 + lrow;
            uint32_t r4[4];
            ldm_x4(r4, sb + 2 * A_TB + nn * 64 + swz64(nn, h));
            bh[2 * jj][0] = r4[0]; bh[2 * jj + 1][0] = r4[1];
            bh[2 * jj][1] = r4[2]; bh[2 * jj + 1][1] = r4[3];
            ldm_x4(r4, sb + 2 * A_TB + B_TB + nn * 64 + swz64(nn, h));
            bl[2 * jj][0] = r4[0]; bl[2 * jj + 1][0] = r4[1];
            bl[2 * jj][1] = r4[2]; bl[2 * jj + 1][1] = r4[3];
        }
        #pragma unroll
        for (int mf = 0; mf < 2; mf++)
            #pragma unroll
            for (int nf = 0; nf < 4; nf++) {
                mma16816(c[mf][nf], ah[mf], bh[nf]);
                mma16816(c[mf][nf], ah[mf], bl[nf]);
                mma16816(c[mf][nf], al[mf], bh[nf]);
            }
    }
}

__global__ __launch_bounds__(256) void out_gemm_mma(
    const float* __restrict__ b_o, float* __restrict__ out)
{
    extern __shared__ __align__(128) char gsm[];
    const int tid  = threadIdx.x;
    const int wid  = tid >> 5;
    const int lane = tid & 31;
    const int wm   = wid & 1;
    const int wn   = wid >> 1;
    const int br   = blockIdx.y * CTA_M;
    const int bc   = blockIdx.x * CTA_N;
    const uint32_t smem = smem_u32(gsm);

    float c[2][4][4];
    #pragma unroll
    for (int i = 0; i < 2; i++)
        #pragma unroll
        for (int j = 0; j < 4; j++)
            #pragma unroll
            for (int q = 0; q < 4; q++) c[i][j][q] = 0.f;

    const int lrow = ((lane >> 3) & 1) * 8 + (lane & 7);
    const int lh   = (lane >> 4) & 1;

    gemm_prefetch(smem, tid, br, bc, 0 * KCHUNK, 0);
    gemm_prefetch(smem, tid, br, bc, 1 * KCHUNK, 1);

    for (int kc = 0; kc < NKC; kc++) {
        if (kc + 2 < NKC) { gemm_prefetch(smem, tid, br, bc, (kc + 2) * KCHUNK, (kc + 2) & 3); CP_WAIT(2); }
        else if (kc + 1 < NKC) { CP_WAIT(1); }
        else { CP_WAIT(0); }
        __syncthreads();                       // single barrier per chunk
        gemm_chunk(smem + (kc & 3) * STAGE_B, wm, wn, lrow, lh, c);
    }

    const int g  = lane >> 2;
    const int tg = lane & 3;
    #pragma unroll
    for (int nf = 0; nf < 4; nf++) {
        const int col = bc + wn * 32 + nf * 8 + tg * 2;
        const float2 bb = *(const float2*)(b_o + col);
        #pragma unroll
        for (int mf = 0; mf < 2; mf++) {
            const int row0 = br + wm * 32 + mf * 16 + g;
            float2 v0 = make_float2(c[mf][nf][0] + bb.x, c[mf][nf][1] + bb.y);
            float2 v1 = make_float2(c[mf][nf][2] + bb.x, c[mf][nf][3] + bb.y);
            *(float2*)(out + (size_t)row0 * OUT_ + col)       = v0;
            *(float2*)(out + (size_t)(row0 + 8) * OUT_ + col) = v1;
        }
    }
}

// ==================================================================
// Launch: conv_B forked onto a side stream, joined before the GEMM.
// ==================================================================
extern "C" void kernel_launch(void* const* d_in, const int* in_sizes, int n_in,
                              void* d_out, int out_size)
{
    const float* x    = (const float*)d_in[0];
    const float* mem  = (const float*)d_in[1];
    const float* W_ar = (const float*)d_in[2];
    const float* b_ar = (const float*)d_in[3];
    const float* W_pr = (const float*)d_in[4];
    const float* b_pr = (const float*)d_in[5];
    const float* W_f  = (const float*)d_in[6];
    const float* b_f  = (const float*)d_in[7];
    const float* W_r  = (const float*)d_in[8];
    const float* b_r  = (const float*)d_in[9];
    const float* W_o  = (const float*)d_in[10];
    const float* b_o  = (const float*)d_in[11];

    float* out     = (float*)d_out;
    float* new_mem = out + (size_t)B_ * OUT_;

    static cudaStream_t s1 = nullptr;
    static cudaEvent_t ev_root = nullptr, ev_side = nullptr;
    if (!s1) {
        cudaStreamCreateWithFlags(&s1, cudaStreamNonBlocking);
        cudaEventCreateWithFlags(&ev_root, cudaEventDisableTiming);
        cudaEventCreateWithFlags(&ev_side, cudaEventDisableTiming);
        cudaFuncSetAttribute(mem_kernel, cudaFuncAttributeMaxDynamicSharedMemorySize, MEM_SMEM);
        cudaFuncSetAttribute(proj_kernel, cudaFuncAttributeMaxDynamicSharedMemorySize, PROJ_SMEM);
        cudaFuncSetAttribute(out_gemm_mma, cudaFuncAttributeMaxDynamicSharedMemorySize, GEMM_SMEM);
    }

    // fork: conv_B on side stream
    cudaEventRecord(ev_root, 0);
    cudaStreamWaitEvent(s1, ev_root, 0);
    {
        dim3 g(KO / 32, OUT_ / 32);
        conv_B_kernel<<<g, 256, 0, s1>>>(W_o);
    }
    cudaEventRecord(ev_side, s1);

    // main chain
    pack_kernel<<<(PACK_TOT + 255) / 256, 256>>>(W_ar, W_f, W_r);
    proj_kernel<<<B_ / GROUP, PTH, PROJ_SMEM>>>(x, b_ar, b_f, b_r);
    mem_kernel<<<B_, MTH, MEM_SMEM>>>(mem, W_pr, b_pr, new_mem);

    // join, then GEMM
    cudaStreamWaitEvent(0, ev_side, 0);
    {
        dim3 g(OUT_ / CTA_N, B_ / CTA_M);   // (16, 8)
        out_gemm_mma<<<g, 256, GEMM_SMEM>>>(b_o, out);
    }
}

// round 14
// speedup vs baseline: 1.3759x; 1.0394x over previous
#include <cuda_runtime.h>
#include <cuda_bf16.h>
#include <math.h>
#include <cstdint>

// Problem constants
#define B_    512
#define NS    128
#define IN_   2048
#define MEM_  64
#define OUT_  2048
#define RCOLS 65
#define KO    2176          // IN_ + 2*MEM_
#define NPAD  132

// ------------------------------------------------------------------
// Scratch (device globals)
// ------------------------------------------------------------------
__device__ float g_q  [B_ * MEM_];      // bias-init by pack, atomicAdd by proj
__device__ float g_xf [B_];
__device__ float g_xr [B_ * RCOLS];
__device__ float g_W  [IN_ * NPAD];
__device__ __nv_bfloat16 g_Ahi[B_ * KO];
__device__ __nv_bfloat16 g_Alo[B_ * KO];
__device__ __nv_bfloat16 g_Bhi[OUT_ * KO];
__device__ __nv_bfloat16 g_Blo[OUT_ * KO];
__device__ __nv_bfloat16 g_WBhi[80 * 64];
__device__ __nv_bfloat16 g_WBlo[80 * 64];

// ------------------------------------------------------------------
// Helpers
// ------------------------------------------------------------------
__device__ __forceinline__ uint32_t smem_u32(const void* p) {
    uint32_t a;
    asm("{ .reg .u64 t; cvta.to.shared.u64 t, %1; cvt.u32.u64 %0, t; }"
        : "=r"(a) : "l"(p));
    return a;
}
__device__ __forceinline__ void cp16(uint32_t dst, const void* src) {
    asm volatile("cp.async.cg.shared.global [%0], [%1], 16;" :: "r"(dst), "l"(src));
}
#define CP_COMMIT()  asm volatile("cp.async.commit_group;" ::: "memory")
#define CP_WAIT(n)   asm volatile("cp.async.wait_group %0;" :: "n"(n) : "memory")

__device__ __forceinline__ void ldm_x4(uint32_t* r, uint32_t addr) {
    asm volatile("ldmatrix.sync.aligned.m8n8.x4.shared.b16 {%0,%1,%2,%3}, [%4];"
        : "=r"(r[0]), "=r"(r[1]), "=r"(r[2]), "=r"(r[3]) : "r"(addr));
}
__device__ __forceinline__ void mma16816(float* c, const uint32_t* a, const uint32_t* b) {
    asm volatile(
        "mma.sync.aligned.m16n8k16.row.col.f32.bf16.bf16.f32 "
        "{%0,%1,%2,%3}, {%4,%5,%6,%7}, {%8,%9}, {%0,%1,%2,%3};"
        : "+f"(c[0]), "+f"(c[1]), "+f"(c[2]), "+f"(c[3])
        : "r"(a[0]), "r"(a[1]), "r"(a[2]), "r"(a[3]), "r"(b[0]), "r"(b[1]));
}
__device__ __forceinline__ void split_bf16(float v, __nv_bfloat16& h, __nv_bfloat16& l) {
    h = __float2bfloat16(v);
    l = __float2bfloat16(v - __bfloat162float(h));
}

// ==================================================================
// Prep: pack weights + bias-init the projection accumulators.
// ==================================================================
#define P_W    (IN_ * NPAD)                   // 270336
#define P_WB   (P_W + 80 * 64)                // 275456
#define P_Q    (P_WB + B_ * MEM_)             // 308224
#define P_XF   (P_Q + B_)                     // 308736
#define P_XR   (P_XF + B_ * RCOLS)            // 342016
__global__ __launch_bounds__(256) void pack_kernel(
    const float* __restrict__ W_ar, const float* __restrict__ W_f,
    const float* __restrict__ W_r,
    const float* __restrict__ b_ar, const float* __restrict__ b_f,
    const float* __restrict__ b_r)
{
    int idx = blockIdx.x * 256 + threadIdx.x;
    if (idx >= P_XR) return;
    if (idx < P_W) {
        int k = idx / NPAD, c = idx - k * NPAD;
        float v = 0.f;
        if (c < 64)       v = W_ar[(size_t)k * 64 + c];
        else if (c == 64) v = W_f[k];
        else if (c < 130) v = W_r[(size_t)k * RCOLS + (c - 65)];
        g_W[idx] = v;
    } else if (idx < P_WB) {
        int e = idx - P_W;
        int j = e >> 6, k = e & 63;
        float v = 0.f;
        if (j < 65)       v = W_r[(size_t)(IN_ + k) * RCOLS + j];
        else if (j == 65) v = W_f[IN_ + k];
        __nv_bfloat16 h, l;
        split_bf16(v, h, l);
        int dst = j * 64 + (((k >> 3) ^ (j & 7)) << 3) + (k & 7);
        g_WBhi[dst] = h;
        g_WBlo[dst] = l;
    } else if (idx < P_Q) {
        int e = idx - P_WB;
        g_q[e] = b_ar[e & 63];
    } else if (idx < P_XF) {
        g_xf[idx - P_Q] = b_f[0];
    } else {
        int e = idx - P_XF;
        g_xr[e] = b_r[e % RCOLS];
    }
}

// W_o [K=2176][N=2048] -> g_B* [N][K] bf16 hi/lo (tiled transpose)
__global__ __launch_bounds__(256) void conv_B_kernel(const float* __restrict__ W_o)
{
    __shared__ float t[32][33];
    const int k0 = blockIdx.x * 32;
    const int n0 = blockIdx.y * 32;
    const int tid = threadIdx.x;
    #pragma unroll
    for (int p = 0; p < 4; p++) {
        int r = (tid >> 5) + p * 8, c = tid & 31;
        t[r][c] = W_o[(size_t)(k0 + r) * OUT_ + n0 + c];
    }
    __syncthreads();
    #pragma unroll
    for (int p = 0; p < 2; p++) {
        int r = (tid >> 4) + p * 16;
        int cc = (tid & 15) * 2;
        float v0 = t[cc][r], v1 = t[cc + 1][r];
        __nv_bfloat16 h0, l0, h1, l1;
        split_bf16(v0, h0, l0);
        split_bf16(v1, h1, l1);
        __nv_bfloat162 hp; hp.x = h0; hp.y = h1;
        __nv_bfloat162 lp; lp.x = l0; lp.y = l1;
        *(__nv_bfloat162*)(g_Bhi + (size_t)(n0 + r) * KO + k0 + cc) = hp;
        *(__nv_bfloat162*)(g_Blo + (size_t)(n0 + r) * KO + k0 + cc) = lp;
    }
}

// ==================================================================
// Kernel A: projections, GROUP=8 batches x 2 k-halves (halved
// weight traffic), atomicAdd combine onto bias-initialized outputs.
// Also converts x -> bf16 hi/lo for its k-half.
// ==================================================================
#define GROUP 8
#define KHALF (IN_ / 2)           // 1024
#define CW4   33
#define KQ2   16
#define PTH   (CW4 * KQ2)         // 528
#define KSLC  (KHALF / KQ2)       // 64

__global__ __launch_bounds__(PTH) void proj_kernel(const float* __restrict__ x)
{
    extern __shared__ float psm[];
    float* xs  = psm;                       // [GROUP][KHALF]    32 KB
    float* red = psm + GROUP * KHALF;       // [GROUP][KQ2][NPAD] 67.6 KB
    const int b0 = blockIdx.x * GROUP;
    const int kh = blockIdx.y;              // 0 or 1
    const int kofs = kh * KHALF;

    for (int i = threadIdx.x; i < GROUP * (KHALF / 4); i += PTH) {
        int g = i >> 8, k4 = i & 255;
        ((float4*)(xs + g * KHALF))[k4] =
            ((const float4*)(x + (size_t)(b0 + g) * IN_ + kofs))[k4];
    }
    __syncthreads();

    // x -> bf16 hi/lo for this k-half
    for (int i = threadIdx.x; i < GROUP * (KHALF / 8); i += PTH) {
        int g = i >> 7, c8 = (i & 127) << 3;
        __nv_bfloat16 h[8], l[8];
        #pragma unroll
        for (int j = 0; j < 8; j++) split_bf16(xs[g * KHALF + c8 + j], h[j], l[j]);
        *(uint4*)(g_Ahi + (size_t)(b0 + g) * KO + kofs + c8) = *(const uint4*)h;
        *(uint4*)(g_Alo + (size_t)(b0 + g) * KO + kofs + c8) = *(const uint4*)l;
    }

    const int t  = threadIdx.x;
    const int c4 = t % CW4;
    const int kq = t / CW4;
    const int kbase = kq * KSLC;

    float4 acc[GROUP];
    #pragma unroll
    for (int g = 0; g < GROUP; g++) acc[g] = make_float4(0.f, 0.f, 0.f, 0.f);

    const float4* wp = (const float4*)(g_W + (size_t)(kofs + kbase) * NPAD) + c4;
    #pragma unroll 8
    for (int k = 0; k < KSLC; k++) {
        const float4 w = wp[(size_t)k * (NPAD / 4)];
        const int kk = kbase + k;
        #pragma unroll
        for (int g = 0; g < GROUP; g++) {
            const float xv = xs[g * KHALF + kk];
            acc[g].x = fmaf(xv, w.x, acc[g].x);
            acc[g].y = fmaf(xv, w.y, acc[g].y);
            acc[g].z = fmaf(xv, w.z, acc[g].z);
            acc[g].w = fmaf(xv, w.w, acc[g].w);
        }
    }
    #pragma unroll
    for (int g = 0; g < GROUP; g++)
        *(float4*)&red[(g * KQ2 + kq) * NPAD + c4 * 4] = acc[g];
    __syncthreads();

    if (t < 130) {
        #pragma unroll
        for (int g = 0; g < GROUP; g++) {
            float s = 0.f;
            #pragma unroll
            for (int q = 0; q < KQ2; q++)
                s += red[(g * KQ2 + q) * NPAD + t];
            const int b = b0 + g;
            if (t < 64)       atomicAdd(&g_q[(size_t)b * MEM_ + t], s);
            else if (t == 64) atomicAdd(&g_xf[b], s);
            else              atomicAdd(&g_xr[(size_t)b * RCOLS + (t - 65)], s);
        }
    }
}
#define PROJ_SMEM ((GROUP * KHALF + GROUP * KQ2 * NPAD) * 4)   // 100352

// ==================================================================
// Kernel B: memory-fused (R10/R13 version) with paired reduces.
// ==================================================================
#define MTH   256
#define MSP   68
#define IMG_F    13312
#define TAIL_OFF (8704 + IMG_F)
#define MEM_SMEM ((TAIL_OFF + 1024) * 4)

__device__ __forceinline__ void blockReduce2(
    float& va, float& vb, float* red16, int isSum)
{
    #pragma unroll
    for (int o = 16; o; o >>= 1) {
        float ua = __shfl_xor_sync(0xffffffffu, va, o);
        float ub = __shfl_xor_sync(0xffffffffu, vb, o);
        va = isSum ? (va + ua) : fmaxf(va, ua);
        vb = isSum ? (vb + ub) : fmaxf(vb, ub);
    }
    if ((threadIdx.x & 31) == 0) {
        red16[(threadIdx.x >> 5) * 2]     = va;
        red16[(threadIdx.x >> 5) * 2 + 1] = vb;
    }
    __syncthreads();
    float ra = red16[0], rb = red16[1];
    #pragma unroll
    for (int i = 1; i < 8; i++) {
        ra = isSum ? (ra + red16[2 * i])     : fmaxf(ra, red16[2 * i]);
        rb = isSum ? (rb + red16[2 * i + 1]) : fmaxf(rb, red16[2 * i + 1]);
    }
    __syncthreads();
    va = ra; vb = rb;
}

__global__ __launch_bounds__(MTH) void mem_kernel(
    const float* __restrict__ memory,
    const float* __restrict__ W_pr, const float* __restrict__ b_pr,
    float* __restrict__ new_memory)
{
    extern __shared__ float sm[];
    float* msf   = sm;
    char*  img   = (char*)(sm + 8704);
    float* remS  = (float*)img;
    float* qs    = sm + TAIL_OFF;
    float* wpr   = qs + 64;
    float* xrs   = wpr + 64;
    float* s1    = xrs + 68;
    float* s2    = s1 + 128;
    float* red16 = s2 + 128;      // 16
    float* pad   = red16 + 16;    // 512

    const int b    = blockIdx.x;
    const int t    = threadIdx.x;
    const int wid  = t >> 5;
    const int lane = t & 31;
    const float* memb = memory + (size_t)b * NS * MEM_;
    const float xfv = g_xf[b];

    {
        __nv_bfloat16* Ah = (__nv_bfloat16*)img;
        __nv_bfloat16* Al = (__nv_bfloat16*)(img + 16384);
        for (int i8 = t; i8 < NS * MEM_ / 8; i8 += MTH) {
            const int e = i8 * 8;
            const int n = e >> 6, m = e & 63, q = m >> 3;
            float4 v0 = *(const float4*)(memb + e);
            float4 v1 = *(const float4*)(memb + e + 4);
            *(float4*)&msf[n * MSP + m]     = v0;
            *(float4*)&msf[n * MSP + m + 4] = v1;
            const float vv[8] = {v0.x, v0.y, v0.z, v0.w, v1.x, v1.y, v1.z, v1.w};
            __nv_bfloat16 h[8], l[8];
            #pragma unroll
            for (int j = 0; j < 8; j++) split_bf16(vv[j], h[j], l[j]);
            const int idx = n * 64 + ((q ^ (n & 7)) << 3);
            *(uint4*)(Ah + idx) = *(const uint4*)h;
            *(uint4*)(Al + idx) = *(const uint4*)l;
        }
    }
    {
        const uint4* wbh = (const uint4*)g_WBhi;
        const uint4* wbl = (const uint4*)g_WBlo;
        uint4* Bh = (uint4*)(img + 32768);
        uint4* Bl = (uint4*)(img + 43008);
        for (int i = t; i < 1280; i += MTH) {
            if (i < 640) Bh[i] = wbh[i];
            else         Bl[i - 640] = wbl[i - 640];
        }
    }
    if (t < 64) { qs[t] = g_q[(size_t)b * MEM_ + t]; wpr[t] = W_pr[t]; }
    if (t < 65) { xrs[t] = g_xr[(size_t)b * RCOLS + t]; }
    __syncthreads();

    const uint32_t Abase = smem_u32(img);
    const uint32_t Bbase = Abase + 32768;
    const int rr   = wid * 16;
    const int lrow = ((lane >> 3) & 1) * 8 + (lane & 7);
    const int lh   = (lane >> 4) & 1;

    float c[10][4];
    #pragma unroll
    for (int i = 0; i < 10; i++)
        #pragma unroll
        for (int q = 0; q < 4; q++) c[i][q] = 0.f;

    #pragma unroll
    for (int s = 0; s < 4; s++) {
        const int hb = s * 2 + lh;
        const int arow = rr + lrow;
        const uint32_t aoff = arow * 128 + ((hb ^ (arow & 7)) << 4);
        uint32_t ah[4], al[4];
        ldm_x4(ah, Abase + aoff);
        ldm_x4(al, Abase + 16384 + aoff);
        #pragma unroll
        for (int gp = 0; gp < 5; gp++) {
            const int jr = gp * 16 + lrow;
            const uint32_t boff = jr * 128 + ((hb ^ (jr & 7)) << 4);
            uint32_t r4[4], q4[4];
            ldm_x4(r4, Bbase + boff);
            ldm_x4(q4, Bbase + 10240 + boff);
            uint32_t bh0[2] = {r4[0], r4[2]}, bh1[2] = {r4[1], r4[3]};
            uint32_t bl0[2] = {q4[0], q4[2]}, bl1[2] = {q4[1], q4[3]};
            mma16816(c[gp * 2], ah, bh0);
            mma16816(c[gp * 2], ah, bl0);
            mma16816(c[gp * 2], al, bh0);
            mma16816(c[gp * 2 + 1], ah, bh1);
            mma16816(c[gp * 2 + 1], ah, bl1);
            mma16816(c[gp * 2 + 1], al, bh1);
        }
    }
    __syncthreads();

    float s1v = -1e30f, s2v = -1e30f;
    if (t < NS) {
        float a = 0.f, p = 0.f;
        #pragma unroll
        for (int k4 = 0; k4 < 16; k4++) {
            float4 mv = *(float4*)&msf[t * MSP + k4 * 4];
            a = fmaf(mv.x, qs[k4 * 4 + 0], a);
            a = fmaf(mv.y, qs[k4 * 4 + 1], a);
            a = fmaf(mv.z, qs[k4 * 4 + 2], a);
            a = fmaf(mv.w, qs[k4 * 4 + 3], a);
            p = fmaf(mv.x, wpr[k4 * 4 + 0], p);
            p = fmaf(mv.y, wpr[k4 * 4 + 1], p);
            p = fmaf(mv.z, wpr[k4 * 4 + 2], p);
            p = fmaf(mv.w, wpr[k4 * 4 + 3], p);
        }
        s1v = a;
        s2v = p + b_pr[0];
    }
    float m1 = s1v, m2 = s2v;
    blockReduce2(m1, m2, red16, 0);
    float e1 = (t < NS) ? expf(s1v - m1) : 0.f;
    float e2 = (t < NS) ? expf(s2v - m2) : 0.f;
    float u1 = e1, u2 = e2;
    blockReduce2(u1, u2, red16, 1);
    if (t < NS) { s1[t] = e1 / u1; s2[t] = e2 / u2; }
    __syncthreads();

    {
        const int col = t & 63;
        const int grp = t >> 6;
        float act = 0.f, pas = 0.f;
        #pragma unroll 4
        for (int n = grp * 32; n < grp * 32 + 32; n++) {
            float mv = msf[n * MSP + col];
            act = fmaf(s1[n], mv, act);
            pas = fmaf(s2[n], mv, pas);
        }
        pad[grp * 64 + col]       = act;
        pad[256 + grp * 64 + col] = pas;
    }
    __syncthreads();
    if (t < MEM_) {
        float act = pad[t] + pad[64 + t] + pad[128 + t] + pad[192 + t];
        float pas = pad[256 + t] + pad[320 + t] + pad[384 + t] + pad[448 + t];
        __nv_bfloat16 h, l;
        split_bf16(act, h, l);
        g_Ahi[(size_t)b * KO + IN_ + t] = h;
        g_Alo[(size_t)b * KO + IN_ + t] = l;
        split_bf16(pas, h, l);
        g_Ahi[(size_t)b * KO + IN_ + MEM_ + t] = h;
        g_Alo[(size_t)b * KO + IN_ + MEM_ + t] = l;
    }
    __syncthreads();

    {
        const int g  = lane >> 2;
        const int tg = lane & 3;
        const int r0 = rr + g;
        #pragma unroll
        for (int nf = 0; nf < 10; nf++) {
            const int col = nf * 8 + tg * 2;
            #pragma unroll
            for (int half = 0; half < 2; half++) {
                const int cc = col + half;
                if (cc > 65) continue;
                const float bias = (cc < 65) ? xrs[cc] : 0.f;
                float v0 = c[nf][half]     + bias;
                float v1 = c[nf][half + 2] + bias;
                if (cc == 65) {
                    v0 = 1.1f / (1.f + expf(-(v0 + xfv)));
                    v1 = 1.1f / (1.f + expf(-(v1 + xfv)));
                }
                remS[r0 * 72 + cc]       = v0;
                remS[(r0 + 8) * 72 + cc] = v1;
            }
        }
    }
    __syncthreads();

    float* nm = new_memory + (size_t)b * NS * MEM_;
    for (int i4 = t; i4 < NS * MEM_ / 4; i4 += MTH) {
        int e = i4 * 4;
        int n = e >> 6, m = e & 63;
        const float f    = remS[n * 72 + 65];
        const float gate = remS[n * 72 + 64];
        float4 mv = *(float4*)&msf[n * MSP + m];
        float4 rv = *(float4*)&remS[n * 72 + m];
        float4 o;
        o.x = fmaf(mv.x, f, gate * rv.x);
        o.y = fmaf(mv.y, f, gate * rv.y);
        o.z = fmaf(mv.z, f, gate * rv.z);
        o.w = fmaf(mv.w, f, gate * rv.w);
        *(float4*)(nm + e) = o;
    }
}

// ==================================================================
// Kernel C: mma.sync bf16-split GEMM, 4-stage ring, prefetch dist 2,
// one __syncthreads per chunk (unchanged from R13).
// ==================================================================
#define CTA_M   64
#define CTA_N   128
#define KCHUNK  32
#define NKC     68
#define A_TB    4096
#define B_TB    8192
#define STAGE_B (2 * A_TB + 2 * B_TB)
#define GEMM_SMEM (4 * STAGE_B)

__device__ __forceinline__ uint32_t swz64(int r, int h) {
    return (uint32_t)((h ^ (r & 3) ^ ((r >> 2) & 1)) << 4);
}

__device__ __forceinline__ void gemm_prefetch(
    uint32_t smem, int tid, int br, int bc, int k0, int stage)
{
    const uint32_t sb = smem + stage * STAGE_B;
    #pragma unroll
    for (int q = 0; q < 2; q++) {
        int u = tid + q * 256;
        int tile = u >> 8, rm = u & 255;
        int r = rm >> 2, h = rm & 3;
        const __nv_bfloat16* src =
            (tile ? g_Alo : g_Ahi) + (size_t)(br + r) * KO + k0 + h * 8;
        cp16(sb + tile * A_TB + r * 64 + swz64(r, h), src);
    }
    #pragma unroll
    for (int q = 0; q < 4; q++) {
        int u = tid + q * 256;
        int tile = u >> 9, rm = u & 511;
        int n = rm >> 2, h = rm & 3;
        const __nv_bfloat16* src =
            (tile ? g_Blo : g_Bhi) + (size_t)(bc + n) * KO + k0 + h * 8;
        cp16(sb + 2 * A_TB + tile * B_TB + n * 64 + swz64(n, h), src);
    }
    CP_COMMIT();
}

__device__ __forceinline__ void gemm_chunk(
    uint32_t sb, int wm, int wn, int lrow, int lh, float c[2][4][4])
{
    #pragma unroll
    for (int s = 0; s < 2; s++) {
        const int h = s * 2 + lh;
        uint32_t ah[2][4], al[2][4];
        #pragma unroll
        for (int f = 0; f < 2; f++) {
            int rr = wm * 32 + f * 16 + lrow;
            ldm_x4(ah[f], sb + rr * 64 + swz64(rr, h));
            ldm_x4(al[f], sb + A_TB + rr * 64 + swz64(rr, h));
        }
        uint32_t bh[4][2], bl[4][2];
        #pragma unroll
        for (int jj = 0; jj < 2; jj++) {
            int nn = wn * 32 + jj * 16 + lrow;
            uint32_t r4[4];
            ldm_x4(r4, sb + 2 * A_TB + nn * 64 + swz64(nn, h));
            bh[2 * jj][0] = r4[0]; bh[2 * jj + 1][0] = r4[1];
            bh[2 * jj][1] = r4[2]; bh[2 * jj + 1][1] = r4[3];
            ldm_x4(r4, sb + 2 * A_TB + B_TB + nn * 64 + swz64(nn, h));
            bl[2 * jj][0] = r4[0]; bl[2 * jj + 1][0] = r4[1];
            bl[2 * jj][1] = r4[2]; bl[2 * jj + 1][1] = r4[3];
        }
        #pragma unroll
        for (int mf = 0; mf < 2; mf++)
            #pragma unroll
            for (int nf = 0; nf < 4; nf++) {
                mma16816(c[mf][nf], ah[mf], bh[nf]);
                mma16816(c[mf][nf], ah[mf], bl[nf]);
                mma16816(c[mf][nf], al[mf], bh[nf]);
            }
    }
}

__global__ __launch_bounds__(256) void out_gemm_mma(
    const float* __restrict__ b_o, float* __restrict__ out)
{
    extern __shared__ __align__(128) char gsm[];
    const int tid  = threadIdx.x;
    const int wid  = tid >> 5;
    const int lane = tid & 31;
    const int wm   = wid & 1;
    const int wn   = wid >> 1;
    const int br   = blockIdx.y * CTA_M;
    const int bc   = blockIdx.x * CTA_N;
    const uint32_t smem = smem_u32(gsm);

    float c[2][4][4];
    #pragma unroll
    for (int i = 0; i < 2; i++)
        #pragma unroll
        for (int j = 0; j < 4; j++)
            #pragma unroll
            for (int q = 0; q < 4; q++) c[i][j][q] = 0.f;

    const int lrow = ((lane >> 3) & 1) * 8 + (lane & 7);
    const int lh   = (lane >> 4) & 1;

    gemm_prefetch(smem, tid, br, bc, 0 * KCHUNK, 0);
    gemm_prefetch(smem, tid, br, bc, 1 * KCHUNK, 1);

    for (int kc = 0; kc < NKC; kc++) {
        if (kc + 2 < NKC) { gemm_prefetch(smem, tid, br, bc, (kc + 2) * KCHUNK, (kc + 2) & 3); CP_WAIT(2); }
        else if (kc + 1 < NKC) { CP_WAIT(1); }
        else { CP_WAIT(0); }
        __syncthreads();
        gemm_chunk(smem + (kc & 3) * STAGE_B, wm, wn, lrow, lh, c);
    }

    const int g  = lane >> 2;
    const int tg = lane & 3;
    #pragma unroll
    for (int nf = 0; nf < 4; nf++) {
        const int col = bc + wn * 32 + nf * 8 + tg * 2;
        const float2 bb = *(const float2*)(b_o + col);
        #pragma unroll
        for (int mf = 0; mf < 2; mf++) {
            const int row0 = br + wm * 32 + mf * 16 + g;
            float2 v0 = make_float2(c[mf][nf][0] + bb.x, c[mf][nf][1] + bb.y);
            float2 v1 = make_float2(c[mf][nf][2] + bb.x, c[mf][nf][3] + bb.y);
            *(float2*)(out + (size_t)row0 * OUT_ + col)       = v0;
            *(float2*)(out + (size_t)(row0 + 8) * OUT_ + col) = v1;
        }
    }
}

// ==================================================================
// Launch
// ==================================================================
extern "C" void kernel_launch(void* const* d_in, const int* in_sizes, int n_in,
                              void* d_out, int out_size)
{
    const float* x    = (const float*)d_in[0];
    const float* mem  = (const float*)d_in[1];
    const float* W_ar = (const float*)d_in[2];
    const float* b_ar = (const float*)d_in[3];
    const float* W_pr = (const float*)d_in[4];
    const float* b_pr = (const float*)d_in[5];
    const float* W_f  = (const float*)d_in[6];
    const float* b_f  = (const float*)d_in[7];
    const float* W_r  = (const float*)d_in[8];
    const float* b_r  = (const float*)d_in[9];
    const float* W_o  = (const float*)d_in[10];
    const float* b_o  = (const float*)d_in[11];

    float* out     = (float*)d_out;
    float* new_mem = out + (size_t)B_ * OUT_;

    static cudaStream_t s1 = nullptr;
    static cudaEvent_t ev_root = nullptr, ev_side = nullptr;
    if (!s1) {
        cudaStreamCreateWithFlags(&s1, cudaStreamNonBlocking);
        cudaEventCreateWithFlags(&ev_root, cudaEventDisableTiming);
        cudaEventCreateWithFlags(&ev_side, cudaEventDisableTiming);
        cudaFuncSetAttribute(mem_kernel, cudaFuncAttributeMaxDynamicSharedMemorySize, MEM_SMEM);
        cudaFuncSetAttribute(proj_kernel, cudaFuncAttributeMaxDynamicSharedMemorySize, PROJ_SMEM);
        cudaFuncSetAttribute(out_gemm_mma, cudaFuncAttributeMaxDynamicSharedMemorySize, GEMM_SMEM);
    }

    // fork: conv_B on side stream
    cudaEventRecord(ev_root, 0);
    cudaStreamWaitEvent(s1, ev_root, 0);
    {
        dim3 g(KO / 32, OUT_ / 32);
        conv_B_kernel<<<g, 256, 0, s1>>>(W_o);
    }
    cudaEventRecord(ev_side, s1);

    // main chain
    pack_kernel<<<(P_XR + 255) / 256, 256>>>(W_ar, W_f, W_r, b_ar, b_f, b_r);
    {
        dim3 g(B_ / GROUP, 2);   // (64, 2) = 128 blocks
        proj_kernel<<<g, PTH, PROJ_SMEM>>>(x);
    }
    mem_kernel<<<B_, MTH, MEM_SMEM>>>(mem, W_pr, b_pr, new_mem);

    // join, then GEMM
    cudaStreamWaitEvent(0, ev_side, 0);
    {
        dim3 g(OUT_ / CTA_N, B_ / CTA_M);   // (16, 8)
        out_gemm_mma<<<g, 256, GEMM_SMEM>>>(b_o, out);
    }
}